// round 1
// baseline (speedup 1.0000x reference)
#include <cuda_runtime.h>
#include <math.h>

// Problem constants
#define BQ   4
#define NQ   4096
#define NKV  1024
#define CD   512
#define NH   8
#define HD   64

// Scratch (device globals: allocation-free rule)
__device__ float g_kv  [BQ * NKV * CD];        // 2M  floats
__device__ float g_q   [BQ * NH * NQ  * HD];   // 8M  floats, [b][h][n][d]
__device__ float g_k   [BQ * NH * NKV * HD];   // 2M  floats
__device__ float g_v   [BQ * NH * NKV * HD];   // 2M  floats
__device__ float g_attn[BQ * NQ * CD];         // 8M  floats, [b][n][h*64+d]

// ---------------------------------------------------------------------------
// Generic 64x64 tile GEMM, N fixed to 512. C = A[MxK] * B[KxN] + bias.
// MODE 0: plain row-major store. MODE 1: scatter to head-major [b][h][n][d].
// ---------------------------------------------------------------------------
template <int MODE>
__global__ void gemm64_kernel(const float* __restrict__ A,
                              const float* __restrict__ Bm,
                              const float* __restrict__ bias,
                              float* __restrict__ Cout,
                              int M, int K, int Nrows)
{
    const int N = 512;
    __shared__ float As[16][65];   // [k][m], padded
    __shared__ float Bs[16][64];   // [k][n]

    const int m0  = blockIdx.y * 64;
    const int n0  = blockIdx.x * 64;
    const int tid = threadIdx.x;
    const int tx  = tid & 15;
    const int ty  = tid >> 4;

    const int lrow = tid >> 2;         // 0..63 : A row within tile
    const int lk   = (tid & 3) * 4;    // 0,4,8,12 : A k offset
    const int brow = tid >> 4;         // 0..15 : B k row
    const int bn   = (tid & 15) * 4;   // B n offset

    float acc[4][4];
#pragma unroll
    for (int i = 0; i < 4; i++)
#pragma unroll
        for (int j = 0; j < 4; j++) acc[i][j] = 0.f;

    const float* Arow = A + (size_t)(m0 + lrow) * K;

    for (int k0 = 0; k0 < K; k0 += 16) {
        float4 av = *reinterpret_cast<const float4*>(Arow + k0 + lk);
        As[lk + 0][lrow] = av.x;
        As[lk + 1][lrow] = av.y;
        As[lk + 2][lrow] = av.z;
        As[lk + 3][lrow] = av.w;
        *reinterpret_cast<float4*>(&Bs[brow][bn]) =
            *reinterpret_cast<const float4*>(&Bm[(size_t)(k0 + brow) * N + n0 + bn]);
        __syncthreads();

#pragma unroll
        for (int kk = 0; kk < 16; kk++) {
            float a[4], b[4];
#pragma unroll
            for (int i = 0; i < 4; i++) a[i] = As[kk][ty * 4 + i];
            float4 bv = *reinterpret_cast<const float4*>(&Bs[kk][tx * 4]);
            b[0] = bv.x; b[1] = bv.y; b[2] = bv.z; b[3] = bv.w;
#pragma unroll
            for (int i = 0; i < 4; i++)
#pragma unroll
                for (int j = 0; j < 4; j++) acc[i][j] += a[i] * b[j];
        }
        __syncthreads();
    }

#pragma unroll
    for (int i = 0; i < 4; i++) {
        const int m = m0 + ty * 4 + i;
#pragma unroll
        for (int j = 0; j < 4; j++) {
            const int c   = n0 + tx * 4 + j;
            const float v = acc[i][j] + bias[c];
            if (MODE == 0) {
                Cout[(size_t)m * N + c] = v;
            } else {
                const int b = m / Nrows;
                const int n = m - b * Nrows;
                const int h = c & 7;
                const int d = c >> 3;
                Cout[(((size_t)(b * NH + h) * Nrows + n) * HD) + d] = v;
            }
        }
    }
}

// ---------------------------------------------------------------------------
// SR conv as GEMM with gathered A: M=4096 (b,i,j), K=2048 (di,dj,c), N=512.
// sr_w HWIO flattening is exactly row-major [2048, 512].
// ---------------------------------------------------------------------------
__global__ void conv_gemm_kernel(const float* __restrict__ x,
                                 const float* __restrict__ Wm,
                                 const float* __restrict__ bias,
                                 float* __restrict__ Cout)
{
    const int N = 512, K = 2048;
    __shared__ float As[16][65];
    __shared__ float Bs[16][64];

    const int m0  = blockIdx.y * 64;
    const int n0  = blockIdx.x * 64;
    const int tid = threadIdx.x;
    const int tx  = tid & 15;
    const int ty  = tid >> 4;

    const int lrow = tid >> 2;
    const int lk   = (tid & 3) * 4;
    const int brow = tid >> 4;
    const int bn   = (tid & 15) * 4;

    // decode gathered A row
    const int m   = m0 + lrow;
    const int b   = m >> 10;
    const int rem = m & 1023;
    const int ii  = rem >> 5;
    const int jj  = rem & 31;

    float acc[4][4];
#pragma unroll
    for (int i = 0; i < 4; i++)
#pragma unroll
        for (int j = 0; j < 4; j++) acc[i][j] = 0.f;

    for (int k0 = 0; k0 < K; k0 += 16) {
        const int k   = k0 + lk;
        const int blk = k >> 9;           // 0..3 (di,dj)
        const int c   = k & 511;
        const int di  = blk >> 1;
        const int dj  = blk & 1;
        const float* src =
            x + ((size_t)((b * 64 + 2 * ii + di) * 64 + (2 * jj + dj)) * 512 + c);
        float4 av = *reinterpret_cast<const float4*>(src);
        As[lk + 0][lrow] = av.x;
        As[lk + 1][lrow] = av.y;
        As[lk + 2][lrow] = av.z;
        As[lk + 3][lrow] = av.w;
        *reinterpret_cast<float4*>(&Bs[brow][bn]) =
            *reinterpret_cast<const float4*>(&Wm[(size_t)(k0 + brow) * N + n0 + bn]);
        __syncthreads();

#pragma unroll
        for (int kk = 0; kk < 16; kk++) {
            float a[4], bb[4];
#pragma unroll
            for (int i = 0; i < 4; i++) a[i] = As[kk][ty * 4 + i];
            float4 bv = *reinterpret_cast<const float4*>(&Bs[kk][tx * 4]);
            bb[0] = bv.x; bb[1] = bv.y; bb[2] = bv.z; bb[3] = bv.w;
#pragma unroll
            for (int i = 0; i < 4; i++)
#pragma unroll
                for (int j = 0; j < 4; j++) acc[i][j] += a[i] * bb[j];
        }
        __syncthreads();
    }

#pragma unroll
    for (int i = 0; i < 4; i++) {
        const int mm = m0 + ty * 4 + i;
#pragma unroll
        for (int j = 0; j < 4; j++) {
            const int c = n0 + tx * 4 + j;
            Cout[(size_t)mm * N + c] = acc[i][j] + bias[c];
        }
    }
}

// ---------------------------------------------------------------------------
// LayerNorm in-place over the last dim (512) of g_kv. One block per row.
// ---------------------------------------------------------------------------
__global__ void ln_kernel(float* __restrict__ kv,
                          const float* __restrict__ gam,
                          const float* __restrict__ bet)
{
    __shared__ float red[256];
    const int row = blockIdx.x;
    const int t   = threadIdx.x;
    float* p = kv + (size_t)row * 512;

    float v0 = p[t], v1 = p[t + 256];
    red[t] = v0 + v1;
    __syncthreads();
    for (int o = 128; o > 0; o >>= 1) {
        if (t < o) red[t] += red[t + o];
        __syncthreads();
    }
    const float mu = red[0] * (1.f / 512.f);
    __syncthreads();

    const float d0 = v0 - mu, d1 = v1 - mu;
    red[t] = d0 * d0 + d1 * d1;
    __syncthreads();
    for (int o = 128; o > 0; o >>= 1) {
        if (t < o) red[t] += red[t + o];
        __syncthreads();
    }
    const float var = red[0] * (1.f / 512.f);
    const float r   = rsqrtf(var + 1e-6f);
    p[t]       = d0 * r * gam[t]       + bet[t];
    p[t + 256] = d1 * r * gam[t + 256] + bet[t + 256];
}

// ---------------------------------------------------------------------------
// Flash attention: one block per (b, h, q-tile of 64). 256 threads.
// Q/K/V in head-major [b][h][n][d]. Output -> g_attn[b][n][h*64+d].
// Softmax scale folded into Q load.
// ---------------------------------------------------------------------------
#define FL_QT 0          // Qt[64][65], transposed [d][q]
#define FL_KT 4160       // Kt[64][65], transposed [d][k]
#define FL_SS 8320       // Ss[64][65], natural [q][k]
#define FL_VS 12480      // Vs[64][64], natural [k][d]
#define FL_SMEM_FLOATS 16576

__global__ void flash_kernel(const float* __restrict__ Q,
                             const float* __restrict__ Kk,
                             const float* __restrict__ V,
                             float* __restrict__ Out)
{
    extern __shared__ float sm[];
    float* Qt = sm + FL_QT;
    float* Kt = sm + FL_KT;
    float* Ss = sm + FL_SS;
    float* Vs = sm + FL_VS;

    const int b  = blockIdx.z;
    const int h  = blockIdx.y;
    const int qt = blockIdx.x;

    const float* Qp = Q  + ((size_t)(b * NH + h) * NQ  + qt * 64) * HD;
    const float* Kp = Kk + ((size_t)(b * NH + h) * NKV) * HD;
    const float* Vp = V  + ((size_t)(b * NH + h) * NKV) * HD;

    const int tid = threadIdx.x;
    const int tx  = tid & 15;
    const int ty  = tid >> 4;
    const int lrow = tid >> 2;          // 0..63
    const int ldb  = (tid & 3) * 16;    // 0,16,32,48

    // load Q transposed, fold 1/sqrt(64)=0.125 scale
#pragma unroll
    for (int u = 0; u < 4; u++) {
        float4 q4 = *reinterpret_cast<const float4*>(&Qp[(size_t)lrow * HD + ldb + u * 4]);
        Qt[(ldb + u * 4 + 0) * 65 + lrow] = q4.x * 0.125f;
        Qt[(ldb + u * 4 + 1) * 65 + lrow] = q4.y * 0.125f;
        Qt[(ldb + u * 4 + 2) * 65 + lrow] = q4.z * 0.125f;
        Qt[(ldb + u * 4 + 3) * 65 + lrow] = q4.w * 0.125f;
    }

    float m_run[4], l_run[4];
    float o[4][4];
#pragma unroll
    for (int i = 0; i < 4; i++) {
        m_run[i] = -INFINITY;
        l_run[i] = 0.f;
#pragma unroll
        for (int j = 0; j < 4; j++) o[i][j] = 0.f;
    }

    for (int kt = 0; kt < NKV; kt += 64) {
        __syncthreads();   // protect Kt/Vs/Ss reuse, also orders the Q fill
        // load K transposed, V natural
#pragma unroll
        for (int u = 0; u < 4; u++) {
            float4 k4 = *reinterpret_cast<const float4*>(
                &Kp[(size_t)(kt + lrow) * HD + ldb + u * 4]);
            Kt[(ldb + u * 4 + 0) * 65 + lrow] = k4.x;
            Kt[(ldb + u * 4 + 1) * 65 + lrow] = k4.y;
            Kt[(ldb + u * 4 + 2) * 65 + lrow] = k4.z;
            Kt[(ldb + u * 4 + 3) * 65 + lrow] = k4.w;
            float4 v4 = *reinterpret_cast<const float4*>(
                &Vp[(size_t)(kt + lrow) * HD + ldb + u * 4]);
            *reinterpret_cast<float4*>(&Vs[lrow * 64 + ldb + u * 4]) = v4;
        }
        __syncthreads();

        // S = (Q*scale) K^T
        float s[4][4];
#pragma unroll
        for (int i = 0; i < 4; i++)
#pragma unroll
            for (int j = 0; j < 4; j++) s[i][j] = 0.f;
#pragma unroll
        for (int d = 0; d < 64; d++) {
            float a[4], kkv[4];
#pragma unroll
            for (int i = 0; i < 4; i++) a[i]   = Qt[d * 65 + ty * 4 + i];
#pragma unroll
            for (int j = 0; j < 4; j++) kkv[j] = Kt[d * 65 + tx * 4 + j];
#pragma unroll
            for (int i = 0; i < 4; i++)
#pragma unroll
                for (int j = 0; j < 4; j++) s[i][j] += a[i] * kkv[j];
        }

        // online softmax update (row stats across 16 tx lanes of a half-warp)
#pragma unroll
        for (int i = 0; i < 4; i++) {
            float mx = fmaxf(fmaxf(s[i][0], s[i][1]), fmaxf(s[i][2], s[i][3]));
#pragma unroll
            for (int off = 8; off > 0; off >>= 1)
                mx = fmaxf(mx, __shfl_xor_sync(0xffffffffu, mx, off));
            const float mnew = fmaxf(m_run[i], mx);
            const float corr = __expf(m_run[i] - mnew);
            float rs = 0.f;
#pragma unroll
            for (int j = 0; j < 4; j++) {
                const float pv = __expf(s[i][j] - mnew);
                s[i][j] = pv;
                rs += pv;
            }
#pragma unroll
            for (int off = 8; off > 0; off >>= 1)
                rs += __shfl_xor_sync(0xffffffffu, rs, off);
            l_run[i] = l_run[i] * corr + rs;
            m_run[i] = mnew;
#pragma unroll
            for (int j = 0; j < 4; j++) o[i][j] *= corr;
#pragma unroll
            for (int j = 0; j < 4; j++)
                Ss[(ty * 4 + i) * 65 + tx * 4 + j] = s[i][j];
        }
        __syncthreads();

        // O += P @ V
#pragma unroll
        for (int kk = 0; kk < 64; kk++) {
            float p[4];
#pragma unroll
            for (int i = 0; i < 4; i++) p[i] = Ss[(ty * 4 + i) * 65 + kk];
            float4 v4 = *reinterpret_cast<const float4*>(&Vs[kk * 64 + tx * 4]);
            float vv[4] = {v4.x, v4.y, v4.z, v4.w};
#pragma unroll
            for (int i = 0; i < 4; i++)
#pragma unroll
                for (int j = 0; j < 4; j++) o[i][j] += p[i] * vv[j];
        }
    }

    // normalize and write: Out[b][q][h*64+d]
#pragma unroll
    for (int i = 0; i < 4; i++) {
        const float inv = 1.f / l_run[i];
        const int   qrow = qt * 64 + ty * 4 + i;
        float4 ov;
        ov.x = o[i][0] * inv; ov.y = o[i][1] * inv;
        ov.z = o[i][2] * inv; ov.w = o[i][3] * inv;
        *reinterpret_cast<float4*>(
            &Out[((size_t)b * NQ + qrow) * CD + h * HD + tx * 4]) = ov;
    }
}

// ---------------------------------------------------------------------------
extern "C" void kernel_launch(void* const* d_in, const int* in_sizes, int n_in,
                              void* d_out, int out_size)
{
    const float* x    = (const float*)d_in[0];
    const float* Wq   = (const float*)d_in[1];
    const float* bq   = (const float*)d_in[2];
    const float* Wk   = (const float*)d_in[3];
    const float* bk   = (const float*)d_in[4];
    const float* Wv   = (const float*)d_in[5];
    const float* bv   = (const float*)d_in[6];
    const float* Wp   = (const float*)d_in[7];
    const float* bp   = (const float*)d_in[8];
    const float* sr_w = (const float*)d_in[9];
    const float* sr_b = (const float*)d_in[10];
    const float* ln_g = (const float*)d_in[11];
    const float* ln_b = (const float*)d_in[12];
    float* out = (float*)d_out;

    float *kv, *qb, *kb, *vb, *ab;
    cudaGetSymbolAddress((void**)&kv, g_kv);
    cudaGetSymbolAddress((void**)&qb, g_q);
    cudaGetSymbolAddress((void**)&kb, g_k);
    cudaGetSymbolAddress((void**)&vb, g_v);
    cudaGetSymbolAddress((void**)&ab, g_attn);

    // 1. SR conv (patch GEMM) -> kv_raw
    conv_gemm_kernel<<<dim3(8, 64), 256>>>(x, sr_w, sr_b, kv);
    // 2. LayerNorm in place
    ln_kernel<<<BQ * NKV, 256>>>(kv, ln_g, ln_b);
    // 3. Q/K/V projections -> head-major
    gemm64_kernel<1><<<dim3(8, 256), 256>>>(x,  Wq, bq, qb, BQ * NQ,  CD, NQ);
    gemm64_kernel<1><<<dim3(8, 64),  256>>>(kv, Wk, bk, kb, BQ * NKV, CD, NKV);
    gemm64_kernel<1><<<dim3(8, 64),  256>>>(kv, Wv, bv, vb, BQ * NKV, CD, NKV);
    // 4. flash attention
    const int fl_smem = FL_SMEM_FLOATS * (int)sizeof(float);
    cudaFuncSetAttribute(flash_kernel,
                         cudaFuncAttributeMaxDynamicSharedMemorySize, fl_smem);
    flash_kernel<<<dim3(NQ / 64, NH, BQ), 256, fl_smem>>>(qb, kb, vb, ab);
    // 5. output projection
    gemm64_kernel<0><<<dim3(8, 256), 256>>>(ab, Wp, bp, out, BQ * NQ, CD, 0);
}